// round 8
// baseline (speedup 1.0000x reference)
#include <cuda_runtime.h>
#include <cuda_bf16.h>
#include <cstdint>

// ---------------------------------------------------------------------------
// AdaConv fused kernel set (round 8).
// Shapes: N=8, CH=512, SD=512, H=W=128, NG=64 groups, CIG=8, 3x3 kernels.
// Conv uses pair-duplicated smem layout: all f32x2 operands are aligned
// LDS.64/128 loads -> zero register packing on the ALU pipe.
// ---------------------------------------------------------------------------

typedef unsigned long long ull;

__device__ __forceinline__ ull pack2(float lo, float hi) {
    ull r;
    asm("mov.b64 %0, {%1, %2};" : "=l"(r) : "f"(lo), "f"(hi));
    return r;
}
__device__ __forceinline__ void unpack2(ull v, float& lo, float& hi) {
    asm("mov.b64 {%0, %1}, %2;" : "=f"(lo), "=f"(hi) : "l"(v));
}
__device__ __forceinline__ void fma2(ull& acc, ull a, ull b) {
    asm("fma.rn.f32x2 %0, %1, %2, %0;" : "+l"(acc) : "l"(a), "l"(b));
}

// ------------------------- scratch (device globals) ------------------------
__device__ float g_colT[8 * 9 * 2048];   // im2col of style: [n][t][k]
__device__ float g_spool[8 * 512];       // avg-pooled style
__device__ float g_dw[8 * 4096 * 9];     // depthwise kernels [n][oc][t]
__device__ float g_pwkn[8 * 4096];       // pointwise kernels [n][c*8+j]
__device__ float g_pwbias[8 * 512];      // pointwise bias
__device__ float g_mean[8 * 512];
__device__ float g_rstd[8 * 512];

// ------------------------- K1: im2col + avg pool ---------------------------
__global__ void k_prep1(const float* __restrict__ style) {
    int idx = blockIdx.x * blockDim.x + threadIdx.x;
    const int COLT = 8 * 9 * 2048;
    if (idx < COLT) {
        int n = idx / (9 * 2048);
        int r = idx % (9 * 2048);
        int t = r / 2048;
        int k = r % 2048;
        int c = k >> 2, dy = (k >> 1) & 1, dx = k & 1;
        int ty = t / 3, tx = t % 3;
        g_colT[idx] = style[((n * 512 + c) * 4 + (ty + dy)) * 4 + (tx + dx)];
    } else if (idx < COLT + 4096) {
        int j = idx - COLT;
        const float* p = style + (size_t)j * 16;
        float s = 0.f;
#pragma unroll
        for (int q = 0; q < 16; q++) s += p[q];
        g_spool[j] = s * (1.f / 16.f);
    }
}

// ------------------------- K2: pointwise heads -----------------------------
__global__ void k_prep2(const float* __restrict__ pk_w, const float* __restrict__ pk_b,
                        const float* __restrict__ pb_w, const float* __restrict__ pb_b) {
    int idx = blockIdx.x * blockDim.x + threadIdx.x;
    if (idx < 32768) {
        int n = idx >> 12, oc = idx & 4095;
        const float4* w = (const float4*)(pk_w + (size_t)oc * 512);
        const float4* s = (const float4*)(g_spool + n * 512);
        float acc = pk_b[oc];
#pragma unroll 4
        for (int q = 0; q < 128; q++) {
            float4 a = w[q], b = s[q];
            acc += a.x * b.x + a.y * b.y + a.z * b.z + a.w * b.w;
        }
        g_pwkn[idx] = acc;
    } else if (idx < 32768 + 4096) {
        int j = idx - 32768;
        int n = j >> 9, c = j & 511;
        const float4* w = (const float4*)(pb_w + (size_t)c * 512);
        const float4* s = (const float4*)(g_spool + n * 512);
        float acc = pb_b[c];
#pragma unroll 4
        for (int q = 0; q < 128; q++) {
            float4 a = w[q], b = s[q];
            acc += a.x * b.x + a.y * b.y + a.z * b.z + a.w * b.w;
        }
        g_pwbias[j] = acc;
    }
}

// ------------------------- K3: dw GEMM (4096x72, k=2048) -------------------
__global__ void __launch_bounds__(288) k_dw(const float* __restrict__ dw_w,
                                            const float* __restrict__ dw_b) {
    __shared__ float s_col[9][516];
    int n = blockIdx.x >> 7;
    int ocb = blockIdx.x & 127;
    int tid = threadIdx.x;
    int oc_l = tid / 9, t = tid % 9;
    int oc = ocb * 32 + oc_l;
    const float* wrow = dw_w + (size_t)oc * 2048;
    ull acc = 0ULL;
    for (int kc = 0; kc < 4; kc++) {
        __syncthreads();
        for (int j = tid; j < 9 * 512; j += 288) {
            int tt = j >> 9, kk = j & 511;
            s_col[tt][kk] = g_colT[(n * 9 + tt) * 2048 + kc * 512 + kk];
        }
        __syncthreads();
        const float* wc = wrow + kc * 512;
#pragma unroll 4
        for (int k = 0; k < 512; k += 4) {
            longlong2 w2 = *(const longlong2*)(wc + k);
            longlong2 c2 = *(const longlong2*)(&s_col[t][k]);
            fma2(acc, (ull)w2.x, (ull)c2.x);
            fma2(acc, (ull)w2.y, (ull)c2.y);
        }
    }
    float lo, hi;
    unpack2(acc, lo, hi);
    g_dw[((size_t)n * 4096 + oc) * 9 + t] = lo + hi + dw_b[oc];
}

// ------------------------- K4: instance-norm stats -------------------------
__global__ void __launch_bounds__(256) k_stats(const float* __restrict__ pred) {
    int bc = blockIdx.x;  // n*512+c
    const float4* p = (const float4*)(pred + (size_t)bc * 16384);
    int tid = threadIdx.x;
    float s = 0.f, ss = 0.f;
#pragma unroll
    for (int k = 0; k < 16; k++) {
        float4 v = p[tid + k * 256];
        s += v.x + v.y + v.z + v.w;
        ss += v.x * v.x + v.y * v.y + v.z * v.z + v.w * v.w;
    }
#pragma unroll
    for (int o = 16; o; o >>= 1) {
        s += __shfl_xor_sync(~0u, s, o);
        ss += __shfl_xor_sync(~0u, ss, o);
    }
    __shared__ float ws[8], wss[8];
    if ((tid & 31) == 0) { ws[tid >> 5] = s; wss[tid >> 5] = ss; }
    __syncthreads();
    if (tid == 0) {
        float S = 0.f, SS = 0.f;
#pragma unroll
        for (int w = 0; w < 8; w++) { S += ws[w]; SS += wss[w]; }
        float mean = S * (1.f / 16384.f);
        float var = (SS - S * mean) * (1.f / 16383.f);  // ddof=1
        g_mean[bc] = mean;
        g_rstd[bc] = rsqrtf(var + 1e-5f);
    }
}

// ------------------------- K5: main grouped conv ---------------------------
// grid: (8 tiles [2x x 4y], 512 (n,g)), block 256 threads (16px x 16ty).
// Tile: 64 x 32 output. Thread: 8 oc x 2 rows x 4 cols. acc[8][2][2] ull.
// Input staged as PAIR-DUPLICATED smem (float2 per overlapping pair) so all
// fma2 operands come straight from aligned LDS -> zero packing.
// ic processed in 2 chunks of 4 to fit smem (pairs buffer refilled).
struct ConvSmem {
    float2 pairs[4][34][68];  // [ii][row][rx]: (X[col-1+rx... ], X[+1]); 544B rows
    float2 w2[8][8][9];       // fused+scaled weights [o][i][t], duplicated
    float dw[64][9];
    float kn[64];
    float bias[8];
};

__global__ void __launch_bounds__(256) k_conv(const float* __restrict__ pred,
                                              float* __restrict__ out) {
    extern __shared__ ConvSmem sm[];
    ConvSmem& S = sm[0];

    int gb = blockIdx.y;  // n*64+g
    int n = gb >> 6, g = gb & 63;
    int x0 = (blockIdx.x & 1) * 64;
    int y0 = (blockIdx.x >> 1) * 32;
    int tid = threadIdx.x;
    int cbase = n * 512 + g * 8;

    // stage 1: group dw + pwkn
    for (int idx = tid; idx < 576; idx += 256) {
        int t = idx % 9;
        int r = idx / 9;  // j*8+i
        S.dw[r][t] = g_dw[((size_t)n * 4096 + (g * 8 + (r >> 3)) * 8 + (r & 7)) * 9 + t];
    }
    if (tid < 64)
        S.kn[tid] = g_pwkn[n * 4096 + (g * 8 + (tid >> 3)) * 8 + (tid & 7)];
    __syncthreads();

    // stage 2: fuse W_eff * rstd_i
    for (int idx = tid; idx < 576; idx += 256) {
        int t = idx % 9;
        int r = idx / 9;
        int i = r & 7;
        int o = r >> 3;
        float acc = 0.f;
#pragma unroll
        for (int j = 0; j < 8; j++) acc += S.kn[o * 8 + j] * S.dw[j * 8 + i][t];
        float w = acc * g_rstd[cbase + i];
        S.w2[o][i][t] = make_float2(w, w);
    }
    __syncthreads();

    // stage 3: bias with mean fold
    if (tid < 8) {
        int o = tid;
        float b = g_pwbias[cbase + o];
#pragma unroll
        for (int i = 0; i < 8; i++) {
            float m = g_mean[cbase + i];
            float sw = 0.f;
#pragma unroll
            for (int t = 0; t < 9; t++) sw += S.w2[o][i][t].x;
            b -= sw * m;
        }
        S.bias[o] = b;
    }
    __syncthreads();

    int px = tid & 15;   // 0..15, cols 2px and 2px+32 (two pair-slots)
    int ty = tid >> 4;   // 0..15, output rows 2ty, 2ty+1
    int r0 = 2 * ty;

    // acc init = packed bias
    ull acc[8][2][2];
#pragma unroll
    for (int o = 0; o < 8; o++) {
        float b = S.bias[o];
        ull bb = pack2(b, b);
#pragma unroll
        for (int r = 0; r < 2; r++)
#pragma unroll
            for (int m = 0; m < 2; m++) acc[o][r][m] = bb;
    }

    const float* pbase = pred + (size_t)cbase * 16384;

#pragma unroll 1
    for (int chunk = 0; chunk < 2; chunk++) {
        __syncthreads();  // pairs buffer free (prior chunk consumed)
        // fill pair-duplicated input for ic = chunk*4 .. chunk*4+3
        for (int idx = tid; idx < 4 * 34 * 67; idx += 256) {
            int rx = idx % 67;
            int r = idx / 67;
            int ry = r % 34;
            int ii = r / 34;
            int gy = y0 - 1 + ry;
            gy = gy < 0 ? -gy : (gy > 127 ? 254 - gy : gy);
            int ga = x0 - 1 + rx;
            ga = ga < 0 ? -ga : (ga > 127 ? 254 - ga : ga);
            int gb2 = x0 + rx;
            gb2 = gb2 > 127 ? 254 - gb2 : gb2;
            const float* row = pbase + (size_t)(chunk * 4 + ii) * 16384 + gy * 128;
            S.pairs[ii][ry][rx] = make_float2(row[ga], row[gb2]);
        }
        __syncthreads();

#pragma unroll 1
        for (int ii = 0; ii < 4; ii++) {
            int i = chunk * 4 + ii;
#pragma unroll
            for (int ky = 0; ky < 3; ky++) {
                // input rows r0+ky (out row0), r0+ky+1 (out row1)
                const float2* ra = &S.pairs[ii][r0 + ky][2 * px];
                const float2* rb = &S.pairs[ii][r0 + ky + 1][2 * px];
                ulonglong2 qa0 = *(const ulonglong2*)ra;          // P(2pc),P(2pc+1) m=0
                ull ea0 = *(const ull*)(ra + 2);                  // P(2pc+2)
                ulonglong2 qa1 = *(const ulonglong2*)(ra + 32);   // m=1
                ull ea1 = *(const ull*)(ra + 34);
                ulonglong2 qb0 = *(const ulonglong2*)rb;
                ull eb0 = *(const ull*)(rb + 2);
                ulonglong2 qb1 = *(const ulonglong2*)(rb + 32);
                ull eb1 = *(const ull*)(rb + 34);
#pragma unroll
                for (int o = 0; o < 8; o++) {
                    ull w0 = *(const ull*)&S.w2[o][i][ky * 3 + 0];
                    ull w1 = *(const ull*)&S.w2[o][i][ky * 3 + 1];
                    ull wX = *(const ull*)&S.w2[o][i][ky * 3 + 2];
                    fma2(acc[o][0][0], w0, (ull)qa0.x);
                    fma2(acc[o][0][0], w1, (ull)qa0.y);
                    fma2(acc[o][0][0], wX, ea0);
                    fma2(acc[o][0][1], w0, (ull)qa1.x);
                    fma2(acc[o][0][1], w1, (ull)qa1.y);
                    fma2(acc[o][0][1], wX, ea1);
                    fma2(acc[o][1][0], w0, (ull)qb0.x);
                    fma2(acc[o][1][0], w1, (ull)qb0.y);
                    fma2(acc[o][1][0], wX, eb0);
                    fma2(acc[o][1][1], w0, (ull)qb1.x);
                    fma2(acc[o][1][1], w1, (ull)qb1.y);
                    fma2(acc[o][1][1], wX, eb1);
                }
            }
        }
    }

    // epilogue: acc ull == (col, col+1) little-endian -> direct 8B stores
#pragma unroll
    for (int o = 0; o < 8; o++) {
        float* ob = out + (size_t)(cbase + o) * 16384 + (size_t)(y0 + r0) * 128 + x0;
#pragma unroll
        for (int r = 0; r < 2; r++) {
#pragma unroll
            for (int m = 0; m < 2; m++) {
                *(ull*)(ob + (size_t)r * 128 + 2 * px + 32 * m) = acc[o][r][m];
            }
        }
    }
}

// ------------------------- launch ------------------------------------------
extern "C" void kernel_launch(void* const* d_in, const int* in_sizes, int n_in,
                              void* d_out, int out_size) {
    const float* style = (const float*)d_in[0];
    const float* predicted = (const float*)d_in[1];
    const float* dw_w = (const float*)d_in[2];
    const float* dw_b = (const float*)d_in[3];
    const float* pk_w = (const float*)d_in[4];
    const float* pk_b = (const float*)d_in[5];
    const float* pb_w = (const float*)d_in[6];
    const float* pb_b = (const float*)d_in[7];
    float* out = (float*)d_out;

    (void)in_sizes; (void)n_in; (void)out_size;

    cudaFuncSetAttribute(k_conv, cudaFuncAttributeMaxDynamicSharedMemorySize,
                         (int)sizeof(ConvSmem));

    k_prep1<<<(147456 + 4096 + 255) / 256, 256>>>(style);
    k_prep2<<<(32768 + 4096 + 255) / 256, 256>>>(pk_w, pk_b, pb_w, pb_b);
    k_dw<<<1024, 288>>>(dw_w, dw_b);
    k_stats<<<4096, 256>>>(predicted);
    dim3 cgrid(8, 512);
    k_conv<<<cgrid, 256, sizeof(ConvSmem)>>>(predicted, out);
}

// round 11
// speedup vs baseline: 1.4144x; 1.4144x over previous
#include <cuda_runtime.h>
#include <cuda_bf16.h>
#include <cstdint>

// ---------------------------------------------------------------------------
// AdaConv fused kernel set (round 9).
// Conv uses a SHIFTED-COPY smem layout: each input row stored as
//   A[a] = x[x0-1+a] (a=0..65) and B[j] = A[j+1] (j=0..64),
// so every f32x2 operand (taps kx=0,1,2 of an even output pair c) is an
// aligned LDS.64: A[c], B[c], A[c+2]. Zero register packing in the hot loop.
// ---------------------------------------------------------------------------

typedef unsigned long long ull;

__device__ __forceinline__ ull pack2(float lo, float hi) {
    ull r;
    asm("mov.b64 %0, {%1, %2};" : "=l"(r) : "f"(lo), "f"(hi));
    return r;
}
__device__ __forceinline__ void unpack2(ull v, float& lo, float& hi) {
    asm("mov.b64 {%0, %1}, %2;" : "=f"(lo), "=f"(hi) : "l"(v));
}
__device__ __forceinline__ void fma2(ull& acc, ull a, ull b) {
    asm("fma.rn.f32x2 %0, %1, %2, %0;" : "+l"(acc) : "l"(a), "l"(b));
}

// ------------------------- scratch (device globals) ------------------------
__device__ float g_colT[8 * 9 * 2048];   // im2col of style: [n][t][k]
__device__ float g_spool[8 * 512];       // avg-pooled style
__device__ float g_dw[8 * 4096 * 9];     // depthwise kernels [n][oc][t]
__device__ float g_pwkn[8 * 4096];       // pointwise kernels [n][c*8+j]
__device__ float g_pwbias[8 * 512];      // pointwise bias
__device__ float g_mean[8 * 512];
__device__ float g_rstd[8 * 512];

// ------------------------- K1: im2col + avg pool ---------------------------
__global__ void k_prep1(const float* __restrict__ style) {
    int idx = blockIdx.x * blockDim.x + threadIdx.x;
    const int COLT = 8 * 9 * 2048;
    if (idx < COLT) {
        int n = idx / (9 * 2048);
        int r = idx % (9 * 2048);
        int t = r / 2048;
        int k = r % 2048;
        int c = k >> 2, dy = (k >> 1) & 1, dx = k & 1;
        int ty = t / 3, tx = t % 3;
        g_colT[idx] = style[((n * 512 + c) * 4 + (ty + dy)) * 4 + (tx + dx)];
    } else if (idx < COLT + 4096) {
        int j = idx - COLT;
        const float* p = style + (size_t)j * 16;
        float s = 0.f;
#pragma unroll
        for (int q = 0; q < 16; q++) s += p[q];
        g_spool[j] = s * (1.f / 16.f);
    }
}

// ------------------------- K2: pointwise heads -----------------------------
__global__ void k_prep2(const float* __restrict__ pk_w, const float* __restrict__ pk_b,
                        const float* __restrict__ pb_w, const float* __restrict__ pb_b) {
    int idx = blockIdx.x * blockDim.x + threadIdx.x;
    if (idx < 32768) {
        int n = idx >> 12, oc = idx & 4095;
        const float4* w = (const float4*)(pk_w + (size_t)oc * 512);
        const float4* s = (const float4*)(g_spool + n * 512);
        float acc = pk_b[oc];
#pragma unroll 4
        for (int q = 0; q < 128; q++) {
            float4 a = w[q], b = s[q];
            acc += a.x * b.x + a.y * b.y + a.z * b.z + a.w * b.w;
        }
        g_pwkn[idx] = acc;
    } else if (idx < 32768 + 4096) {
        int j = idx - 32768;
        int n = j >> 9, c = j & 511;
        const float4* w = (const float4*)(pb_w + (size_t)c * 512);
        const float4* s = (const float4*)(g_spool + n * 512);
        float acc = pb_b[c];
#pragma unroll 4
        for (int q = 0; q < 128; q++) {
            float4 a = w[q], b = s[q];
            acc += a.x * b.x + a.y * b.y + a.z * b.z + a.w * b.w;
        }
        g_pwbias[j] = acc;
    }
}

// ------------------------- K3: dw GEMM (4096x72, k=2048) -------------------
__global__ void __launch_bounds__(288) k_dw(const float* __restrict__ dw_w,
                                            const float* __restrict__ dw_b) {
    __shared__ float s_col[9][516];
    int n = blockIdx.x >> 7;
    int ocb = blockIdx.x & 127;
    int tid = threadIdx.x;
    int oc_l = tid / 9, t = tid % 9;
    int oc = ocb * 32 + oc_l;
    const float* wrow = dw_w + (size_t)oc * 2048;
    ull acc = 0ULL;
    for (int kc = 0; kc < 4; kc++) {
        __syncthreads();
        for (int j = tid; j < 9 * 512; j += 288) {
            int tt = j >> 9, kk = j & 511;
            s_col[tt][kk] = g_colT[(n * 9 + tt) * 2048 + kc * 512 + kk];
        }
        __syncthreads();
        const float* wc = wrow + kc * 512;
#pragma unroll 4
        for (int k = 0; k < 512; k += 4) {
            longlong2 w2 = *(const longlong2*)(wc + k);
            longlong2 c2 = *(const longlong2*)(&s_col[t][k]);
            fma2(acc, (ull)w2.x, (ull)c2.x);
            fma2(acc, (ull)w2.y, (ull)c2.y);
        }
    }
    float lo, hi;
    unpack2(acc, lo, hi);
    g_dw[((size_t)n * 4096 + oc) * 9 + t] = lo + hi + dw_b[oc];
}

// ------------------------- K4: instance-norm stats -------------------------
__global__ void __launch_bounds__(256) k_stats(const float* __restrict__ pred) {
    int bc = blockIdx.x;  // n*512+c
    const float4* p = (const float4*)(pred + (size_t)bc * 16384);
    int tid = threadIdx.x;
    float s = 0.f, ss = 0.f;
#pragma unroll
    for (int k = 0; k < 16; k++) {
        float4 v = p[tid + k * 256];
        s += v.x + v.y + v.z + v.w;
        ss += v.x * v.x + v.y * v.y + v.z * v.z + v.w * v.w;
    }
#pragma unroll
    for (int o = 16; o; o >>= 1) {
        s += __shfl_xor_sync(~0u, s, o);
        ss += __shfl_xor_sync(~0u, ss, o);
    }
    __shared__ float ws[8], wss[8];
    if ((tid & 31) == 0) { ws[tid >> 5] = s; wss[tid >> 5] = ss; }
    __syncthreads();
    if (tid == 0) {
        float S = 0.f, SS = 0.f;
#pragma unroll
        for (int w = 0; w < 8; w++) { S += ws[w]; SS += wss[w]; }
        float mean = S * (1.f / 16384.f);
        float var = (SS - S * mean) * (1.f / 16383.f);  // ddof=1
        g_mean[bc] = mean;
        g_rstd[bc] = rsqrtf(var + 1e-5f);
    }
}

// ------------------------- K5: main grouped conv ---------------------------
// grid: (16 tiles [2x x 8y], 512 (n,g)), block 128 threads (16px x 8ty).
// Tile: 64 x 16 output. Thread: 8 oc x 2 rows x 2 col-pairs.
// ic in 2 chunks of 4 (smem refilled). smem ~45KB -> 4-5 blocks/SM.
// Row layout: A[0..65] = x[x0-1 .. x0+64], B[j]=A[j+1] at offset 66.
struct ConvSmem {
    float in[4][18][132];    // A at [0..65], B at [66..130]; stride 528B (16B mult)
    float2 w2[8][8][9];      // fused+scaled weights [o][i][t], duplicated halves
    float dw[64][9];
    float kn[64];
    float bias[8];
};

__global__ void __launch_bounds__(128) k_conv(const float* __restrict__ pred,
                                              float* __restrict__ out) {
    extern __shared__ ConvSmem sm[];
    ConvSmem& S = sm[0];

    int gb = blockIdx.y;  // n*64+g
    int n = gb >> 6, g = gb & 63;
    int x0 = (blockIdx.x & 1) * 64;
    int y0 = (blockIdx.x >> 1) * 16;
    int tid = threadIdx.x;
    int cbase = n * 512 + g * 8;

    // stage 1: group dw + pwkn
    for (int idx = tid; idx < 576; idx += 128) {
        int t = idx % 9;
        int r = idx / 9;  // j*8+i
        S.dw[r][t] = g_dw[((size_t)n * 4096 + (g * 8 + (r >> 3)) * 8 + (r & 7)) * 9 + t];
    }
    if (tid < 64)
        S.kn[tid] = g_pwkn[n * 4096 + (g * 8 + (tid >> 3)) * 8 + (tid & 7)];
    __syncthreads();

    // stage 2: fuse W_eff * rstd_i
    for (int idx = tid; idx < 576; idx += 128) {
        int t = idx % 9;
        int r = idx / 9;
        int i = r & 7;
        int o = r >> 3;
        float acc = 0.f;
#pragma unroll
        for (int j = 0; j < 8; j++) acc += S.kn[o * 8 + j] * S.dw[j * 8 + i][t];
        float w = acc * g_rstd[cbase + i];
        S.w2[o][i][t] = make_float2(w, w);
    }
    __syncthreads();

    // stage 3: bias with mean fold
    if (tid < 8) {
        int o = tid;
        float b = g_pwbias[cbase + o];
#pragma unroll
        for (int i = 0; i < 8; i++) {
            float m = g_mean[cbase + i];
            float sw = 0.f;
#pragma unroll
            for (int t = 0; t < 9; t++) sw += S.w2[o][i][t].x;
            b -= sw * m;
        }
        S.bias[o] = b;
    }

    int px = tid & 15;   // col pairs at c0=2px, c1=2px+32
    int ty = tid >> 4;   // 0..7 -> output rows 2ty, 2ty+1 (tile-local)
    int r0 = 2 * ty;
    const int c0 = 2 * px, c1 = 2 * px + 32;

    // acc init = packed bias (read after stage-3 barrier below)
    __syncthreads();
    ull acc[8][2][2];
#pragma unroll
    for (int o = 0; o < 8; o++) {
        float b = S.bias[o];
        ull bb = pack2(b, b);
#pragma unroll
        for (int r = 0; r < 2; r++)
#pragma unroll
            for (int m = 0; m < 2; m++) acc[o][r][m] = bb;
    }

    const float* pbase = pred + (size_t)cbase * 16384;

#pragma unroll 1
    for (int chunk = 0; chunk < 2; chunk++) {
        __syncthreads();  // prior chunk fully consumed
        // fill A + shifted copy B for ic = chunk*4 .. chunk*4+3 (1 LDG, 2 STS)
        for (int idx = tid; idx < 4 * 18 * 66; idx += 128) {
            int rx = idx % 66;
            int r = idx / 66;
            int ry = r % 18;
            int ii = r / 18;
            int gy = y0 - 1 + ry;
            gy = gy < 0 ? -gy : (gy > 127 ? 254 - gy : gy);
            int gx = x0 - 1 + rx;
            gx = gx < 0 ? -gx : (gx > 127 ? 254 - gx : gx);
            float v = pbase[(size_t)(chunk * 4 + ii) * 16384 + gy * 128 + gx];
            S.in[ii][ry][rx] = v;                       // A[rx]
            if (rx >= 1) S.in[ii][ry][66 + rx - 1] = v; // B[rx-1] = A[rx]
        }
        __syncthreads();

#pragma unroll 1
        for (int ii = 0; ii < 4; ii++) {
            int i = chunk * 4 + ii;
#pragma unroll
            for (int ky = 0; ky < 3; ky++) {
                const float* ra = S.in[ii][r0 + ky];      // feeds out row r0
                const float* rb = S.in[ii][r0 + 1 + ky];  // feeds out row r0+1
                // aligned 8B operands: kx0 -> A[c], kx1 -> B[c], kx2 -> A[c+2]
                ull a0_0 = *(const ull*)(ra + c0);
                ull a1_0 = *(const ull*)(ra + 66 + c0);
                ull a2_0 = *(const ull*)(ra + c0 + 2);
                ull a0_1 = *(const ull*)(ra + c1);
                ull a1_1 = *(const ull*)(ra + 66 + c1);
                ull a2_1 = *(const ull*)(ra + c1 + 2);
                ull b0_0 = *(const ull*)(rb + c0);
                ull b1_0 = *(const ull*)(rb + 66 + c0);
                ull b2_0 = *(const ull*)(rb + c0 + 2);
                ull b0_1 = *(const ull*)(rb + c1);
                ull b1_1 = *(const ull*)(rb + 66 + c1);
                ull b2_1 = *(const ull*)(rb + c1 + 2);
#pragma unroll
                for (int o = 0; o < 8; o++) {
                    ull w0 = *(const ull*)&S.w2[o][i][ky * 3 + 0];
                    ull w1 = *(const ull*)&S.w2[o][i][ky * 3 + 1];
                    ull w2 = *(const ull*)&S.w2[o][i][ky * 3 + 2];
                    fma2(acc[o][0][0], w0, a0_0);
                    fma2(acc[o][0][0], w1, a1_0);
                    fma2(acc[o][0][0], w2, a2_0);
                    fma2(acc[o][0][1], w0, a0_1);
                    fma2(acc[o][0][1], w1, a1_1);
                    fma2(acc[o][0][1], w2, a2_1);
                    fma2(acc[o][1][0], w0, b0_0);
                    fma2(acc[o][1][0], w1, b1_0);
                    fma2(acc[o][1][0], w2, b2_0);
                    fma2(acc[o][1][1], w0, b0_1);
                    fma2(acc[o][1][1], w1, b1_1);
                    fma2(acc[o][1][1], w2, b2_1);
                }
            }
        }
    }

    // epilogue: direct 8B stores (acc pair == (col, col+1) little-endian)
#pragma unroll
    for (int o = 0; o < 8; o++) {
        float* ob = out + (size_t)(cbase + o) * 16384 + (size_t)(y0 + r0) * 128 + x0;
#pragma unroll
        for (int r = 0; r < 2; r++) {
            *(ull*)(ob + (size_t)r * 128 + c0) = acc[o][r][0];
            *(ull*)(ob + (size_t)r * 128 + c1) = acc[o][r][1];
        }
    }
}

// ------------------------- launch ------------------------------------------
extern "C" void kernel_launch(void* const* d_in, const int* in_sizes, int n_in,
                              void* d_out, int out_size) {
    const float* style = (const float*)d_in[0];
    const float* predicted = (const float*)d_in[1];
    const float* dw_w = (const float*)d_in[2];
    const float* dw_b = (const float*)d_in[3];
    const float* pk_w = (const float*)d_in[4];
    const float* pk_b = (const float*)d_in[5];
    const float* pb_w = (const float*)d_in[6];
    const float* pb_b = (const float*)d_in[7];
    float* out = (float*)d_out;

    (void)in_sizes; (void)n_in; (void)out_size;

    cudaFuncSetAttribute(k_conv, cudaFuncAttributeMaxDynamicSharedMemorySize,
                         (int)sizeof(ConvSmem));

    k_prep1<<<(147456 + 4096 + 255) / 256, 256>>>(style);
    k_prep2<<<(32768 + 4096 + 255) / 256, 256>>>(pk_w, pk_b, pb_w, pb_b);
    k_dw<<<1024, 288>>>(dw_w, dw_b);
    k_stats<<<4096, 256>>>(predicted);
    dim3 cgrid(16, 512);
    k_conv<<<cgrid, 128, sizeof(ConvSmem)>>>(predicted, out);
}